// round 7
// baseline (speedup 1.0000x reference)
#include <cuda_runtime.h>
#include <cstddef>

// Axial attention on a 7x7 grid (N=512, Cq=64, Cv=512).
// out[n,c,h,w] = sum_j p[n,h,w,j]   * vH[(n*7+w), c, j]
//             + sum_y p[n,h,w,7+y] * vW[(n*7+h), c, y]
// p = softmax over 14 of [eH (diag-masked, transposed), eW].

#define NEGV (-1e20f)
#define MAXN 1024

// finished probabilities: p[n][ pH:49*8 | pW:49*8 ]  (j slot 7 = padding 0)
__device__ float g_p[(size_t)MAXN * 784];

// ---------------------------------------------------------------------------
// Kernel A: logits (both passes) + softmax, one block per n, 704 threads.
// Threads [0,352) stage the H pass, [352,704) the W pass, in parallel.
// q staged [a][row][c], k transposed [a][j][c]; strides 484/68 (==4 mod 32).
// ---------------------------------------------------------------------------
#define ASTRIDE 484
#define RSTRIDE 68
#define QS0 0
#define KT0 3388
#define QS1 6776
#define KT1 10164
#define LG_OFF 13552
#define SMEMA_FLOATS 14240          // 13552 + 686 + pad
#define SMEMA_BYTES (SMEMA_FLOATS * 4)

__global__ __launch_bounds__(704) void ax_logits(
    const float* __restrict__ qH, const float* __restrict__ kH,
    const float* __restrict__ qW, const float* __restrict__ kW)
{
    extern __shared__ float sm[];
    const int n   = blockIdx.x;
    const int tid = threadIdx.x;

    // ---- stage both passes in parallel (352 threads each) ----
    {
        const int half = tid >= 352;
        const int t    = tid - half * 352;
        const float* qsrc = (half ? qW : qH) + (size_t)n * 3136;
        const float* ksrc = (half ? kW : kH) + (size_t)n * 3136;
        float* qs = sm + (half ? QS1 : QS0);
        float* kt = sm + (half ? KT1 : KT0);
        for (int i = t; i < 3136; i += 352) {
            int a = i / 448, r = i % 448, row = r / 64, c = r % 64;
            qs[a * ASTRIDE + row * RSTRIDE + c] = qsrc[i];
        }
        for (int i = t; i < 3136; i += 352) {
            int a = i / 448, r = i % 448, c = r / 7, j = r % 7;
            kt[a * ASTRIDE + j * RSTRIDE + c] = ksrc[i];
        }
    }
    __syncthreads();

    // ---- 686 dots, one per thread ----
    if (tid < 686) {
        const int pass = tid >= 343;
        const int t    = tid - pass * 343;
        const int h = t / 49, rem = t % 49, w = rem / 7, j = rem % 7;
        const int a   = pass ? h : w;
        const int row = pass ? w : h;
        const float4* q4 = (const float4*)(sm + (pass ? QS1 : QS0)
                                           + a * ASTRIDE + row * RSTRIDE);
        const float4* k4 = (const float4*)(sm + (pass ? KT1 : KT0)
                                           + a * ASTRIDE + j * RSTRIDE);
        float4 s = make_float4(0.f, 0.f, 0.f, 0.f);
        #pragma unroll
        for (int kk = 0; kk < 16; kk++) {
            float4 x = q4[kk], y = k4[kk];
            s.x += x.x * y.x; s.y += x.y * y.y;
            s.z += x.z * y.z; s.w += x.w * y.w;
        }
        float v = (s.x + s.y) + (s.z + s.w);
        if (pass == 0 && h == j) v = NEGV;
        sm[LG_OFF + (h * 7 + w) * 14 + pass * 7 + j] = v;
    }
    __syncthreads();

    // ---- softmax over 14 + write p to global ----
    if (tid < 49) {
        const float* row = sm + LG_OFF + tid * 14;
        float m = row[0];
        #pragma unroll
        for (int s = 1; s < 14; s++) m = fmaxf(m, row[s]);
        float e[14];
        float sum = 0.f;
        #pragma unroll
        for (int s = 0; s < 14; s++) { e[s] = __expf(row[s] - m); sum += e[s]; }
        const float inv = 1.f / sum;

        float* gp = g_p + (size_t)n * 784;
        float4 h0 = make_float4(e[0] * inv, e[1] * inv, e[2] * inv, e[3] * inv);
        float4 h1 = make_float4(e[4] * inv, e[5] * inv, e[6] * inv, 0.f);
        float4 w0 = make_float4(e[7] * inv, e[8] * inv, e[9] * inv, e[10] * inv);
        float4 w1 = make_float4(e[11] * inv, e[12] * inv, e[13] * inv, 0.f);
        ((float4*)gp)[tid * 2]             = h0;
        ((float4*)gp)[tid * 2 + 1]         = h1;
        ((float4*)(gp + 392))[tid * 2]     = w0;
        ((float4*)(gp + 392))[tid * 2 + 1] = w1;
    }
}

// ---------------------------------------------------------------------------
// Kernel B: PV contraction. Block = (c-chunk of 128, n), 128 threads.
// v chunks staged DENSELY into smem (pure float4 copy, coalesced), then each
// thread reads its 7 values at smem offset tid*7+j: gcd(7,32)=1 -> 32 lanes
// hit 32 distinct banks -> 1 wavefront per LDS (vs 7 per strided LDG before).
// p reads are warp-uniform LDS.128 broadcasts. Output bounces through smem
// (aliasing the v buffer) for coalesced STG.
// ---------------------------------------------------------------------------
#define CHUNK 128
#define VB_OFF 784                   // after pHs[392] + pWs[392]
#define CPADB 129                    // odd stride -> conflict-free bounce read
#define SMEMB_FLOATS (784 + 49 * CPADB)   // 784 + 6321 = 7105
#define SMEMB_BYTES (SMEMB_FLOATS * 4)

__global__ __launch_bounds__(128, 6) void ax_pv(
    const float* __restrict__ vH, const float* __restrict__ vW,
    float* __restrict__ out, int Cv)
{
    extern __shared__ float sm[];
    float* pHs  = sm;                // [49][8]
    float* pWs  = sm + 392;          // [49][8]
    float* vbuf = sm + VB_OFF;       // 7*896 floats; later aliased by bounce

    const int n   = blockIdx.y;
    const int c0  = blockIdx.x * CHUNK;
    const int tid = threadIdx.x;

    // ---- load probabilities (784 floats) ----
    {
        const float4* src = (const float4*)(g_p + (size_t)n * 784);
        float4* dst = (float4*)sm;
        for (int i = tid; i < 196; i += 128) dst[i] = src[i];
    }

    const size_t bstr = (size_t)Cv * 7;          // b-slice stride (floats)

    // ---- stage vH chunk: dense float4 copy, slice w -> vbuf + w*896 ----
    {
        const float* base = vH + (size_t)n * 7 * bstr + (size_t)c0 * 7;
        for (int i = tid; i < 1568; i += 128) {
            int w = i / 224, r = i % 224;
            ((float4*)(vbuf + w * 896))[r] =
                ((const float4*)(base + (size_t)w * bstr))[r];
        }
    }
    __syncthreads();

    float acc[49];

    // ---- H stage: acc[h*7+w] = sum_j pH[h,w,j] * vh[w][j] ----
    #pragma unroll
    for (int w = 0; w < 7; w++) {
        const float* vp = vbuf + w * 896 + tid * 7;
        float v0 = vp[0], v1 = vp[1], v2 = vp[2], v3 = vp[3],
              v4 = vp[4], v5 = vp[5], v6 = vp[6];
        #pragma unroll
        for (int h = 0; h < 7; h++) {
            const float4 p0 = *(const float4*)(pHs + (h * 7 + w) * 8);
            const float4 p1 = *(const float4*)(pHs + (h * 7 + w) * 8 + 4);
            acc[h * 7 + w] = p0.x * v0 + p0.y * v1 + p0.z * v2 + p0.w * v3
                           + p1.x * v4 + p1.y * v5 + p1.z * v6;
        }
    }
    __syncthreads();

    // ---- stage vW chunk over the same buffer ----
    {
        const float* base = vW + (size_t)n * 7 * bstr + (size_t)c0 * 7;
        for (int i = tid; i < 1568; i += 128) {
            int w = i / 224, r = i % 224;
            ((float4*)(vbuf + w * 896))[r] =
                ((const float4*)(base + (size_t)w * bstr))[r];
        }
    }
    __syncthreads();

    // ---- W stage: acc[h*7+w] += sum_y pW[h,w,y] * vw[h][y] ----
    #pragma unroll
    for (int h = 0; h < 7; h++) {
        const float* vp = vbuf + h * 896 + tid * 7;
        float v0 = vp[0], v1 = vp[1], v2 = vp[2], v3 = vp[3],
              v4 = vp[4], v5 = vp[5], v6 = vp[6];
        #pragma unroll
        for (int w = 0; w < 7; w++) {
            const float4 p0 = *(const float4*)(pWs + (h * 7 + w) * 8);
            const float4 p1 = *(const float4*)(pWs + (h * 7 + w) * 8 + 4);
            acc[h * 7 + w] += p0.x * v0 + p0.y * v1 + p0.z * v2 + p0.w * v3
                            + p1.x * v4 + p1.y * v5 + p1.z * v6;
        }
    }
    __syncthreads();    // vbuf reads done -> safe to overwrite with bounce

    // ---- bounce [hw][c] (STS: lanes consecutive c -> conflict-free) ----
    float* bnc = sm + VB_OFF;
    #pragma unroll
    for (int hw = 0; hw < 49; hw++) bnc[hw * CPADB + tid] = acc[hw];
    __syncthreads();

    // ---- coalesced global store ----
    {
        float* ob = out + ((size_t)n * Cv + c0) * 49;
        int cc = tid / 49;
        int hw = tid - cc * 49;
        for (int i = tid; i < CHUNK * 49; i += 128) {
            ob[i] = bnc[hw * CPADB + cc];
            hw += 30; cc += 2;               // 128 = 2*49 + 30
            if (hw >= 49) { hw -= 49; cc += 1; }
        }
    }
}

extern "C" void kernel_launch(void* const* d_in, const int* in_sizes, int n_in,
                              void* d_out, int out_size)
{
    const float* qH = (const float*)d_in[0];
    const float* kH = (const float*)d_in[1];
    const float* vH = (const float*)d_in[2];
    const float* qW = (const float*)d_in[3];
    const float* kW = (const float*)d_in[4];
    const float* vW = (const float*)d_in[5];

    int N  = in_sizes[0] / (49 * 64);
    int Cv = in_sizes[2] / (N * 49);

    static bool attr_done = false;
    if (!attr_done) {
        cudaFuncSetAttribute(ax_logits,
                             cudaFuncAttributeMaxDynamicSharedMemorySize,
                             SMEMA_BYTES);
        cudaFuncSetAttribute(ax_pv,
                             cudaFuncAttributeMaxDynamicSharedMemorySize,
                             SMEMB_BYTES);
        attr_done = true;
    }

    ax_logits<<<N, 704, SMEMA_BYTES>>>(qH, kH, qW, kW);

    dim3 gb((Cv + CHUNK - 1) / CHUNK, N);
    ax_pv<<<gb, 128, SMEMB_BYTES>>>(vH, vW, (float*)d_out, Cv);
}

// round 8
// speedup vs baseline: 1.5589x; 1.5589x over previous
#include <cuda_runtime.h>
#include <cstdint>
#include <cstddef>

// Axial attention on a 7x7 grid (N=512, Cq=64, Cv=512).
// out[n,c,h,w] = sum_j p[n,h,w,j]   * vH[(n*7+w), c, j]
//             + sum_y p[n,h,w,7+y] * vW[(n*7+h), c, y]
// p = softmax over 14 of [eH (diag-masked, transposed), eW].

#define NEGV (-1e20f)
#define MAXN 1024

// raw logits scratch: lg[n][h*7+w][14]  ([0:7) = H slot, [7:14) = W slot)
__device__ float g_lg[(size_t)MAXN * 49 * 14];

static __device__ __forceinline__ uint32_t s2u(const void* p) {
    return (uint32_t)__cvta_generic_to_shared(p);
}
#define CP_ASYNC16(dst_u32, src_ptr) \
    asm volatile("cp.async.cg.shared.global [%0], [%1], 16;" \
                 :: "r"(dst_u32), "l"(src_ptr))
#define CP_COMMIT()  asm volatile("cp.async.commit_group;")
#define CP_WAIT0()   asm volatile("cp.async.wait_group 0;")

// ---------------------------------------------------------------------------
// Kernel A: raw logits. Block = (n, pass), 256 threads. pass 0 = H, 1 = W.
// q,k staged as STRAIGHT float4 copies (no transpose, no per-element div/mod)
// with slice stride 452 floats (113 float4, ==4 mod 32 for bank spread).
// Dot: q via float4, k strided c*7+j from the natural [c][j] layout:
//   pass0: k addr = 452*w + 7c + j -> <=2-way bank conflicts
//   pass1: k addr lane-dependence is j only -> broadcast, 1 wavefront.
// ---------------------------------------------------------------------------
#define SL 452                       // slice stride (floats)
#define KOFF (7 * SL)                // k region offset (floats)

__global__ __launch_bounds__(256) void ax_logits(
    const float* __restrict__ qH, const float* __restrict__ kH,
    const float* __restrict__ qW, const float* __restrict__ kW)
{
    __shared__ float sm[2 * 7 * SL];  // q then k, 6328 floats = 25.3 KB

    const int n    = blockIdx.x;
    const int pass = blockIdx.y;
    const int tid  = threadIdx.x;

    const float4* q4 = (const float4*)((pass ? qW : qH) + (size_t)n * 3136);
    const float4* k4 = (const float4*)((pass ? kW : kH) + (size_t)n * 3136);
    float4* qs4 = (float4*)sm;            // stride 113 f4 per slice
    float4* ks4 = (float4*)(sm + KOFF);

    for (int i = tid; i < 784; i += 256) {
        int a = i / 112, r = i - a * 112;
        qs4[a * 113 + r] = q4[i];
        ks4[a * 113 + r] = k4[i];
    }
    __syncthreads();

    for (int t = tid; t < 343; t += 256) {
        const int h = t / 49, rem = t % 49, w = rem / 7, j = rem % 7;
        const int a   = pass ? h : w;
        const int row = pass ? w : h;
        const float* qp = sm + a * SL + row * 64;
        const float* kp = sm + KOFF + a * SL + j;
        float s = 0.f;
        #pragma unroll
        for (int c = 0; c < 64; c += 4) {
            float4 x = *(const float4*)(qp + c);
            s += x.x * kp[c * 7]       + x.y * kp[(c + 1) * 7]
               + x.z * kp[(c + 2) * 7] + x.w * kp[(c + 3) * 7];
        }
        if (pass == 0 && h == j) s = NEGV;
        g_lg[(size_t)n * 686 + (size_t)(h * 7 + w) * 14 + pass * 7 + j] = s;
    }
}

// ---------------------------------------------------------------------------
// Kernel B: softmax + PV contraction. Block = (c-chunk of 128, n), 128 thr.
// BOTH v chunks cp.async'd into separate smem buffers up front (no register
// roundtrip, one wait) while logits load + softmax overlap. H and W compute
// run back-to-back with no sync between. Thread = channel: v LDS at tid*7+j
// (gcd(7,32)=1 -> conflict-free), p reads warp-uniform broadcasts. Output
// bounces through smem (aliasing vh) for coalesced STG.
// ---------------------------------------------------------------------------
#define CHUNK  128
#define PH_OFF 0
#define PW_OFF 392
#define LG_OFF 784                    // 688 slot (686 used)
#define VH_OFF 1472                   // 6272
#define VW_OFF 7744                   // 6272
#define BN_OFF 1472                   // bounce aliases vh (+49 into vw)
#define CPADB  129
#define SMEMB_FLOATS 14016            // 56064 B -> 4 blocks/SM
#define SMEMB_BYTES (SMEMB_FLOATS * 4)

__global__ __launch_bounds__(128, 4) void ax_pv(
    const float* __restrict__ vH, const float* __restrict__ vW,
    float* __restrict__ out, int Cv)
{
    extern __shared__ float sm[];
    float* pHs = sm + PH_OFF;
    float* pWs = sm + PW_OFF;
    float* lg  = sm + LG_OFF;

    const int n   = blockIdx.y;
    const int c0  = blockIdx.x * CHUNK;
    const int tid = threadIdx.x;

    const size_t bstr = (size_t)Cv * 7;   // b-slice stride (floats)
    const uint32_t smb = s2u(sm);

    // ---- issue ALL v cp.asyncs first (vh then vw), single group ----
    {
        const float* bh = vH + (size_t)n * 7 * bstr + (size_t)c0 * 7;
        const float* bw = vW + (size_t)n * 7 * bstr + (size_t)c0 * 7;
        for (int i = tid; i < 1568; i += 128) {
            int w = i / 224, r = i - w * 224;
            CP_ASYNC16(smb + (VH_OFF + w * 896 + r * 4) * 4,
                       bh + w * bstr + r * 4);
            CP_ASYNC16(smb + (VW_OFF + w * 896 + r * 4) * 4,
                       bw + w * bstr + r * 4);
        }
        CP_COMMIT();
    }

    // ---- logits load (overlaps the async copies) ----
    {
        const float* gl = g_lg + (size_t)n * 686;
        for (int i = tid; i < 686; i += 128) lg[i] = gl[i];
    }
    __syncthreads();

    // ---- softmax over 14 ----
    if (tid < 49) {
        const float* row = lg + tid * 14;
        float m = row[0];
        #pragma unroll
        for (int s = 1; s < 14; s++) m = fmaxf(m, row[s]);
        float e[14];
        float sum = 0.f;
        #pragma unroll
        for (int s = 0; s < 14; s++) { e[s] = __expf(row[s] - m); sum += e[s]; }
        const float inv = 1.f / sum;
        #pragma unroll
        for (int s = 0; s < 7; s++) {
            pHs[tid * 8 + s] = e[s]     * inv;
            pWs[tid * 8 + s] = e[s + 7] * inv;
        }
        pHs[tid * 8 + 7] = 0.f;
        pWs[tid * 8 + 7] = 0.f;
    }

    CP_WAIT0();
    __syncthreads();

    float acc[49];

    // ---- H stage: acc[h*7+w] = sum_j pH[h,w,j] * vh[w][tid][j] ----
    #pragma unroll
    for (int w = 0; w < 7; w++) {
        const float* vp = sm + VH_OFF + w * 896 + tid * 7;
        float v0 = vp[0], v1 = vp[1], v2 = vp[2], v3 = vp[3],
              v4 = vp[4], v5 = vp[5], v6 = vp[6];
        #pragma unroll
        for (int h = 0; h < 7; h++) {
            const float4 p0 = *(const float4*)(pHs + (h * 7 + w) * 8);
            const float4 p1 = *(const float4*)(pHs + (h * 7 + w) * 8 + 4);
            acc[h * 7 + w] = p0.x * v0 + p0.y * v1 + p0.z * v2 + p0.w * v3
                           + p1.x * v4 + p1.y * v5 + p1.z * v6;
        }
    }

    // ---- W stage (no sync needed: different buffer) ----
    #pragma unroll
    for (int h = 0; h < 7; h++) {
        const float* vp = sm + VW_OFF + h * 896 + tid * 7;
        float v0 = vp[0], v1 = vp[1], v2 = vp[2], v3 = vp[3],
              v4 = vp[4], v5 = vp[5], v6 = vp[6];
        #pragma unroll
        for (int w = 0; w < 7; w++) {
            const float4 p0 = *(const float4*)(pWs + (h * 7 + w) * 8);
            const float4 p1 = *(const float4*)(pWs + (h * 7 + w) * 8 + 4);
            acc[h * 7 + w] += p0.x * v0 + p0.y * v1 + p0.z * v2 + p0.w * v3
                            + p1.x * v4 + p1.y * v5 + p1.z * v6;
        }
    }
    __syncthreads();     // all reads of vh done -> safe to bounce over it

    float* bnc = sm + BN_OFF;
    #pragma unroll
    for (int hw = 0; hw < 49; hw++) bnc[hw * CPADB + tid] = acc[hw];
    __syncthreads();

    {
        float* ob = out + ((size_t)n * Cv + c0) * 49;
        int cc = tid / 49;
        int hw = tid - cc * 49;
        for (int i = tid; i < CHUNK * 49; i += 128) {
            ob[i] = bnc[hw * CPADB + cc];
            hw += 30; cc += 2;               // 128 = 2*49 + 30
            if (hw >= 49) { hw -= 49; cc += 1; }
        }
    }
}

extern "C" void kernel_launch(void* const* d_in, const int* in_sizes, int n_in,
                              void* d_out, int out_size)
{
    const float* qH = (const float*)d_in[0];
    const float* kH = (const float*)d_in[1];
    const float* vH = (const float*)d_in[2];
    const float* qW = (const float*)d_in[3];
    const float* kW = (const float*)d_in[4];
    const float* vW = (const float*)d_in[5];

    int N  = in_sizes[0] / (49 * 64);
    int Cv = in_sizes[2] / (N * 49);

    static bool attr_done = false;
    if (!attr_done) {
        cudaFuncSetAttribute(ax_pv,
                             cudaFuncAttributeMaxDynamicSharedMemorySize,
                             SMEMB_BYTES);
        attr_done = true;
    }

    dim3 ga(N, 2);
    ax_logits<<<ga, 256>>>(qH, kH, qW, kW);

    dim3 gb((Cv + CHUNK - 1) / CHUNK, N);
    ax_pv<<<gb, 128, SMEMB_BYTES>>>(vH, vW, (float*)d_out, Cv);
}

// round 9
// speedup vs baseline: 1.6628x; 1.0667x over previous
#include <cuda_runtime.h>
#include <cstdint>
#include <cstddef>

// Axial attention on a 7x7 grid (N=512, Cq=64, Cv=512).
// out[n,c,h,w] = sum_j p[n,h,w,j]   * vH[(n*7+w), c, j]
//             + sum_y p[n,h,w,7+y] * vW[(n*7+h), c, y]
// p = softmax over 14 of [eH (diag-masked, transposed), eW].

#define NEGV (-1e20f)
#define MAXN 1024

// raw logits scratch: lg[n][h*7+w][14]  ([0:7) = H slot, [7:14) = W slot)
__device__ float g_lg[(size_t)MAXN * 49 * 14];

static __device__ __forceinline__ uint32_t s2u(const void* p) {
    return (uint32_t)__cvta_generic_to_shared(p);
}
#define CP_ASYNC16(dst_u32, src_ptr) \
    asm volatile("cp.async.cg.shared.global [%0], [%1], 16;" \
                 :: "r"(dst_u32), "l"(src_ptr))
#define CP_COMMIT()  asm volatile("cp.async.commit_group;")
#define CP_WAIT0()   asm volatile("cp.async.wait_group 0;")

// ---------------------------------------------------------------------------
// Kernel A: raw logits. Block = (n, pass), 256 threads. pass 0 = H, 1 = W.
// (unchanged from previous round)
// ---------------------------------------------------------------------------
#define SL 452
#define KOFF (7 * SL)

__global__ __launch_bounds__(256) void ax_logits(
    const float* __restrict__ qH, const float* __restrict__ kH,
    const float* __restrict__ qW, const float* __restrict__ kW)
{
    __shared__ float sm[2 * 7 * SL];

    const int n    = blockIdx.x;
    const int pass = blockIdx.y;
    const int tid  = threadIdx.x;

    const float4* q4 = (const float4*)((pass ? qW : qH) + (size_t)n * 3136);
    const float4* k4 = (const float4*)((pass ? kW : kH) + (size_t)n * 3136);
    float4* qs4 = (float4*)sm;
    float4* ks4 = (float4*)(sm + KOFF);

    for (int i = tid; i < 784; i += 256) {
        int a = i / 112, r = i - a * 112;
        qs4[a * 113 + r] = q4[i];
        ks4[a * 113 + r] = k4[i];
    }
    __syncthreads();

    for (int t = tid; t < 343; t += 256) {
        const int h = t / 49, rem = t % 49, w = rem / 7, j = rem % 7;
        const int a   = pass ? h : w;
        const int row = pass ? w : h;
        const float* qp = sm + a * SL + row * 64;
        const float* kp = sm + KOFF + a * SL + j;
        float s = 0.f;
        #pragma unroll
        for (int c = 0; c < 64; c += 4) {
            float4 x = *(const float4*)(qp + c);
            s += x.x * kp[c * 7]       + x.y * kp[(c + 1) * 7]
               + x.z * kp[(c + 2) * 7] + x.w * kp[(c + 3) * 7];
        }
        if (pass == 0 && h == j) s = NEGV;
        g_lg[(size_t)n * 686 + (size_t)(h * 7 + w) * 14 + pass * 7 + j] = s;
    }
}

// ---------------------------------------------------------------------------
// Kernel B: softmax + PV. Block = (c-chunk of 128, n), 256 threads.
// Thread = (c = tid&127, half = tid>>7). Half 0 computes h in [0,4),
// half 1 h in [4,7): live accumulators drop 49 -> <=28, letting 4 blocks
// (32 warps) fit per SM at 56KB smem. cp.async both v buffers up front;
// softmax overlaps the copies. v LDS at c*7+j is conflict-free; p reads are
// warp-uniform broadcasts. Output bounces through smem for coalesced STG.
// ---------------------------------------------------------------------------
#define CHUNK  128
#define PH_OFF 0
#define PW_OFF 392
#define LG_OFF 784
#define VH_OFF 1472
#define VW_OFF 7744
#define BN_OFF 1472
#define CPADB  129
#define SMEMB_FLOATS 14016
#define SMEMB_BYTES (SMEMB_FLOATS * 4)

template<int HBASE, int NH>
static __device__ __forceinline__ void pv_compute(
    const float* __restrict__ sm, int c, float acc[4][7])
{
    const float* pHs = sm + PH_OFF;
    const float* pWs = sm + PW_OFF;

    // H stage: acc[hh][w] = sum_j pH[HBASE+hh, w, j] * vh[w][c][j]
    #pragma unroll
    for (int w = 0; w < 7; w++) {
        const float* vp = sm + VH_OFF + w * 896 + c * 7;
        float v0 = vp[0], v1 = vp[1], v2 = vp[2], v3 = vp[3],
              v4 = vp[4], v5 = vp[5], v6 = vp[6];
        #pragma unroll
        for (int hh = 0; hh < NH; hh++) {
            const int h = HBASE + hh;
            const float4 p0 = *(const float4*)(pHs + (h * 7 + w) * 8);
            const float4 p1 = *(const float4*)(pHs + (h * 7 + w) * 8 + 4);
            acc[hh][w] = p0.x * v0 + p0.y * v1 + p0.z * v2 + p0.w * v3
                       + p1.x * v4 + p1.y * v5 + p1.z * v6;
        }
    }
    // W stage: acc[hh][w] += sum_y pW[HBASE+hh, w, y] * vw[h][c][y]
    #pragma unroll
    for (int hh = 0; hh < NH; hh++) {
        const int h = HBASE + hh;
        const float* vp = sm + VW_OFF + h * 896 + c * 7;
        float v0 = vp[0], v1 = vp[1], v2 = vp[2], v3 = vp[3],
              v4 = vp[4], v5 = vp[5], v6 = vp[6];
        #pragma unroll
        for (int w = 0; w < 7; w++) {
            const float4 p0 = *(const float4*)(pWs + (h * 7 + w) * 8);
            const float4 p1 = *(const float4*)(pWs + (h * 7 + w) * 8 + 4);
            acc[hh][w] += p0.x * v0 + p0.y * v1 + p0.z * v2 + p0.w * v3
                        + p1.x * v4 + p1.y * v5 + p1.z * v6;
        }
    }
}

__global__ __launch_bounds__(256, 4) void ax_pv(
    const float* __restrict__ vH, const float* __restrict__ vW,
    float* __restrict__ out, int Cv)
{
    extern __shared__ float sm[];
    float* pHs = sm + PH_OFF;
    float* pWs = sm + PW_OFF;
    float* lg  = sm + LG_OFF;

    const int n    = blockIdx.y;
    const int c0   = blockIdx.x * CHUNK;
    const int tid  = threadIdx.x;
    const int c    = tid & 127;
    const int half = tid >> 7;

    const size_t bstr = (size_t)Cv * 7;
    const uint32_t smb = s2u(sm);

    // ---- issue ALL v cp.asyncs first, single group ----
    {
        const float* bh = vH + (size_t)n * 7 * bstr + (size_t)c0 * 7;
        const float* bw = vW + (size_t)n * 7 * bstr + (size_t)c0 * 7;
        for (int i = tid; i < 1568; i += 256) {
            int w = i / 224, r = i - w * 224;
            CP_ASYNC16(smb + (VH_OFF + w * 896 + r * 4) * 4,
                       bh + w * bstr + r * 4);
            CP_ASYNC16(smb + (VW_OFF + w * 896 + r * 4) * 4,
                       bw + w * bstr + r * 4);
        }
        CP_COMMIT();
    }

    // ---- logits load (overlaps the async copies) ----
    {
        const float* gl = g_lg + (size_t)n * 686;
        for (int i = tid; i < 686; i += 256) lg[i] = gl[i];
    }
    __syncthreads();

    // ---- softmax over 14 ----
    if (tid < 49) {
        const float* row = lg + tid * 14;
        float m = row[0];
        #pragma unroll
        for (int s = 1; s < 14; s++) m = fmaxf(m, row[s]);
        float e[14];
        float sum = 0.f;
        #pragma unroll
        for (int s = 0; s < 14; s++) { e[s] = __expf(row[s] - m); sum += e[s]; }
        const float inv = 1.f / sum;
        #pragma unroll
        for (int s = 0; s < 7; s++) {
            pHs[tid * 8 + s] = e[s]     * inv;
            pWs[tid * 8 + s] = e[s + 7] * inv;
        }
        pHs[tid * 8 + 7] = 0.f;
        pWs[tid * 8 + 7] = 0.f;
    }

    CP_WAIT0();
    __syncthreads();

    float acc[4][7];
    if (half == 0) pv_compute<0, 4>(sm, c, acc);
    else           pv_compute<4, 3>(sm, c, acc);

    __syncthreads();     // all v reads done -> safe to bounce over vh

    float* bnc = sm + BN_OFF;
    if (half == 0) {
        #pragma unroll
        for (int hh = 0; hh < 4; hh++)
            #pragma unroll
            for (int w = 0; w < 7; w++)
                bnc[(hh * 7 + w) * CPADB + c] = acc[hh][w];
    } else {
        #pragma unroll
        for (int hh = 0; hh < 3; hh++)
            #pragma unroll
            for (int w = 0; w < 7; w++)
                bnc[((hh + 4) * 7 + w) * CPADB + c] = acc[hh][w];
    }
    __syncthreads();

    {
        float* ob = out + ((size_t)n * Cv + c0) * 49;
        int cc = tid / 49;
        int hw = tid - cc * 49;
        for (int i = tid; i < CHUNK * 49; i += 256) {
            ob[i] = bnc[hw * CPADB + cc];
            hw += 11; cc += 5;               // 256 = 5*49 + 11
            if (hw >= 49) { hw -= 49; cc += 1; }
        }
    }
}

extern "C" void kernel_launch(void* const* d_in, const int* in_sizes, int n_in,
                              void* d_out, int out_size)
{
    const float* qH = (const float*)d_in[0];
    const float* kH = (const float*)d_in[1];
    const float* vH = (const float*)d_in[2];
    const float* qW = (const float*)d_in[3];
    const float* kW = (const float*)d_in[4];
    const float* vW = (const float*)d_in[5];

    int N  = in_sizes[0] / (49 * 64);
    int Cv = in_sizes[2] / (N * 49);

    static bool attr_done = false;
    if (!attr_done) {
        cudaFuncSetAttribute(ax_pv,
                             cudaFuncAttributeMaxDynamicSharedMemorySize,
                             SMEMB_BYTES);
        attr_done = true;
    }

    dim3 ga(N, 2);
    ax_logits<<<ga, 256>>>(qH, kH, qW, kW);

    dim3 gb((Cv + CHUNK - 1) / CHUNK, N);
    ax_pv<<<gb, 256, SMEMB_BYTES>>>(vH, vW, (float*)d_out, Cv);
}